// round 5
// baseline (speedup 1.0000x reference)
#include <cuda_runtime.h>
#include <cstdint>

using ull = unsigned long long;

#define VOC 95
#define TT  256
#define NW  8     // warps per block (2 per SMSP)
#define NT  (NW * 32)
#define NB  128   // blocks

// shared layout (float offsets)
#define OFF_W1I 0        // [3][24][32][4] = 9216
#define OFF_W1H 9216     // [3][8][32][4]  = 3072
#define OFF_W2I 12288
#define OFF_W2H 15360
#define OFF_W3I 18432
#define OFF_W3H 21504
#define OFF_WFC 24576    // 3072
#define OFF_XS  27648    // float2 xs[8 warps][2 buf][96]  = 1536 f2 = 3072 floats
#define OFF_HS  30720    // float2 hs[8 warps][3 layer][32] = 768 f2 = 1536 floats
#define SMEM_FLOATS 32256
#define SMEM_BYTES  (SMEM_FLOATS * 4)

extern __shared__ float smem[];

// ---------- packed fp32x2 helpers ----------
__device__ __forceinline__ ull pk2(float w) {
    ull d; unsigned r = __float_as_uint(w);
    asm("mov.b64 %0, {%1,%1};" : "=l"(d) : "r"(r));
    return d;
}
__device__ __forceinline__ ull pkf(float a, float b) {
    ull d;
    asm("mov.b64 %0, {%1,%2};" : "=l"(d)
        : "r"(__float_as_uint(a)), "r"(__float_as_uint(b)));
    return d;
}
__device__ __forceinline__ float2 up2(ull v) {
    unsigned lo, hi;
    asm("mov.b64 {%0,%1}, %2;" : "=r"(lo), "=r"(hi) : "l"(v));
    return make_float2(__uint_as_float(lo), __uint_as_float(hi));
}
__device__ __forceinline__ void fma2(ull& d, ull a, ull b) {
    asm("fma.rn.f32x2 %0, %1, %2, %0;" : "+l"(d) : "l"(a), "l"(b));
}
__device__ __forceinline__ ull add2(ull a, ull b) {
    ull d; asm("add.rn.f32x2 %0, %1, %2;" : "=l"(d) : "l"(a), "l"(b));
    return d;
}

// ---------- activations (MUFU tanh.approx; ~1e-4 abs err, budget 1e-3) ----------
__device__ __forceinline__ float tanhap(float v) {
    float r; asm("tanh.approx.f32 %0, %1;" : "=f"(r) : "f"(v)); return r;
}
__device__ __forceinline__ float fsig(float v) {
    return fmaf(tanhap(0.5f * v), 0.5f, 0.5f);
}

// ---------- 3-gate projection, one packed row-pair, C 4-wide input chunks ----
// W layout: [gate(3)][chunk(C)][lane(32)][4]; lane j owns output unit j of each gate.
template<int C>
__device__ __forceinline__ void proj3(const float* __restrict__ W, int j,
                                      const float2* __restrict__ in,
                                      ull& aA, ull& aB, ull& aC)
{
    float4 nA = *(const float4*)(W + ((0 * C + 0) * 32 + j) * 4);
    float4 nB = *(const float4*)(W + ((1 * C + 0) * 32 + j) * 4);
    float4 nC = *(const float4*)(W + ((2 * C + 0) * 32 + j) * 4);
    ulonglong2 nx01 = *(const ulonglong2*)(in);
    ulonglong2 nx23 = *(const ulonglong2*)(in + 2);
#pragma unroll 4
    for (int c = 0; c < C; c++) {
        float4 wA = nA, wB = nB, wC = nC;
        ulonglong2 x01 = nx01, x23 = nx23;
        if (c + 1 < C) {
            nA = *(const float4*)(W + ((0 * C + c + 1) * 32 + j) * 4);
            nB = *(const float4*)(W + ((1 * C + c + 1) * 32 + j) * 4);
            nC = *(const float4*)(W + ((2 * C + c + 1) * 32 + j) * 4);
            nx01 = *(const ulonglong2*)(in + 4 * (c + 1));
            nx23 = *(const ulonglong2*)(in + 4 * (c + 1) + 2);
        }
        ull w;
        w = pk2(wA.x); fma2(aA, x01.x, w);
        w = pk2(wA.y); fma2(aA, x01.y, w);
        w = pk2(wA.z); fma2(aA, x23.x, w);
        w = pk2(wA.w); fma2(aA, x23.y, w);
        w = pk2(wB.x); fma2(aB, x01.x, w);
        w = pk2(wB.y); fma2(aB, x01.y, w);
        w = pk2(wB.z); fma2(aB, x23.x, w);
        w = pk2(wB.w); fma2(aB, x23.y, w);
        w = pk2(wC.x); fma2(aC, x01.x, w);
        w = pk2(wC.y); fma2(aC, x01.y, w);
        w = pk2(wC.z); fma2(aC, x23.x, w);
        w = pk2(wC.w); fma2(aC, x23.y, w);
    }
}

// ---------- GRU elementwise for one packed row-pair ----------
__device__ __forceinline__ ull gru_pair(ull aR, ull aZ, ull aNx, ull aNh, ull h)
{
    float2 r2 = up2(aR), z2 = up2(aZ), nx = up2(aNx), nh = up2(aNh), hh = up2(h);
    float r0 = fsig(r2.x), r1 = fsig(r2.y);
    float z0 = fsig(z2.x), z1 = fsig(z2.y);
    float n0 = tanhap(nx.x + r0 * nh.x);
    float n1 = tanhap(nx.y + r1 * nh.y);
    float h0 = n0 + z0 * (hh.x - n0);
    float h1 = n1 + z1 * (hh.y - n1);
    return pkf(h0, h1);
}

// One GRU layer step for this warp's row-pair. hbuf: float2[32].
template<int C>
__device__ __forceinline__ void layer_step(const float* __restrict__ Wi,
                                           const float* __restrict__ Wh,
                                           const float2* __restrict__ in,
                                           float2* hbuf, int j,
                                           ull biR, ull biZ, ull biN,
                                           ull bhR, ull bhZ, ull bhN)
{
    ull xR = biR, xZ = biZ, xN = biN;
    proj3<C>(Wi, j, in, xR, xZ, xN);
    ull hR = bhR, hZ = bhZ, hN = bhN;
    proj3<8>(Wh, j, hbuf, hR, hZ, hN);
    ull h = *(const ull*)(hbuf + j);
    __syncwarp();   // all lanes done reading old h before overwrite
    ull n = gru_pair(add2(xR, hR), add2(xZ, hZ), xN, hN, h);
    *(ull*)(hbuf + j) = n;
    __syncwarp();   // new h visible to all lanes
}

// GMEM weight [3*32, isz] -> SMEM [g][c][lane][4] (i >= isz zero-padded)
__device__ __forceinline__ void load_wmat(float* dst, const float* __restrict__ src,
                                          int C, int isz, int tid)
{
    int n = 3 * C * 128;
    for (int idx = tid; idx < n; idx += NT) {
        int q = idx & 3, jj = (idx >> 2) & 31;
        int c = (idx >> 7) % C, g = idx / (C * 128);
        int i = c * 4 + q;
        dst[idx] = (i < isz) ? src[(g * 32 + jj) * isz + i] : 0.f;
    }
}

__global__ void __launch_bounds__(NT, 1)
gru_fused(const float* __restrict__ x,
          const float* __restrict__ Wih1, const float* __restrict__ Whh1,
          const float* __restrict__ bih1, const float* __restrict__ bhh1,
          const float* __restrict__ Wih2, const float* __restrict__ Whh2,
          const float* __restrict__ bih2, const float* __restrict__ bhh2,
          const float* __restrict__ Wih3, const float* __restrict__ Whh3,
          const float* __restrict__ bih3, const float* __restrict__ bhh3,
          const float* __restrict__ Wfc,  const float* __restrict__ bfc,
          float* __restrict__ out)
{
    const int tid = threadIdx.x;

    // ---- cooperative weight permute into SMEM ----
    load_wmat(smem + OFF_W1I, Wih1, 24, VOC, tid);
    load_wmat(smem + OFF_W1H, Whh1, 8, 32, tid);
    load_wmat(smem + OFF_W2I, Wih2, 8, 32, tid);
    load_wmat(smem + OFF_W2H, Whh2, 8, 32, tid);
    load_wmat(smem + OFF_W3I, Wih3, 8, 32, tid);
    load_wmat(smem + OFF_W3H, Whh3, 8, 32, tid);
    {   // FC: output o = g*32+j (pad o=95), input k = c*4+q; src Wfc[o*32+k]
        float* dst = smem + OFF_WFC;
        for (int idx = tid; idx < 3 * 8 * 128; idx += NT) {
            int q = idx & 3, jj = (idx >> 2) & 31;
            int c = (idx >> 7) % 8, g = idx / (8 * 128);
            int o = g * 32 + jj, k = c * 4 + q;
            dst[idx] = (o < VOC) ? Wfc[o * 32 + k] : 0.f;
        }
    }
    // zero x-stage + h-stage (h0 = 0; xs[95] stays 0 forever)
    for (int idx = tid; idx < SMEM_FLOATS - OFF_XS; idx += NT)
        smem[OFF_XS + idx] = 0.f;
    __syncthreads();

    const int w = tid >> 5, j = tid & 31;
    const int gp = blockIdx.x * NW + w;   // global pair index
    const int r0 = gp * 2;                // this warp's two batch rows
    const int r1 = r0 + 1;

    float2* xsw = (float2*)(smem + OFF_XS) + (size_t)w * (2 * 96);
    float2* hsw = (float2*)(smem + OFF_HS) + (size_t)w * (3 * 32);

    // per-lane bias packs
    ull bi1R = pk2(bih1[j]), bi1Z = pk2(bih1[32 + j]), bi1N = pk2(bih1[64 + j]);
    ull bh1R = pk2(bhh1[j]), bh1Z = pk2(bhh1[32 + j]), bh1N = pk2(bhh1[64 + j]);
    ull bi2R = pk2(bih2[j]), bi2Z = pk2(bih2[32 + j]), bi2N = pk2(bih2[64 + j]);
    ull bh2R = pk2(bhh2[j]), bh2Z = pk2(bhh2[32 + j]), bh2N = pk2(bhh2[64 + j]);
    ull bi3R = pk2(bih3[j]), bi3Z = pk2(bih3[32 + j]), bi3N = pk2(bih3[64 + j]);
    ull bh3R = pk2(bhh3[j]), bh3Z = pk2(bhh3[32 + j]), bh3N = pk2(bhh3[64 + j]);
    float bf0 = (j      < VOC) ? bfc[j]      : 0.f;
    float bf1 = (32 + j < VOC) ? bfc[32 + j] : 0.f;
    float bf2 = (64 + j < VOC) ? bfc[64 + j] : 0.f;
    ull bfc0 = pk2(bf0), bfc1 = pk2(bf1), bfc2 = pk2(bf2);

    // ---- prologue: stage x[t=0] into buffer 0 ----
#pragma unroll
    for (int k = 0; k < 3; k++) {
        int i = j + 32 * k;
        if (i < VOC) {
            float a = __ldcs(x + ((size_t)r0 * TT + 0) * VOC + i);
            float b = __ldcs(x + ((size_t)r1 * TT + 0) * VOC + i);
            xsw[i] = make_float2(a, b);
        }
    }
    __syncwarp();

#pragma unroll 1
    for (int t = 0; t < TT; t++) {
        // prefetch x[t+1] into registers (latency hidden by compute)
        float pa[3], pb[3];
        const int tn = t + 1;
        if (tn < TT) {
#pragma unroll
            for (int k = 0; k < 3; k++) {
                int i = j + 32 * k;
                if (i < VOC) {
                    pa[k] = __ldcs(x + ((size_t)r0 * TT + tn) * VOC + i);
                    pb[k] = __ldcs(x + ((size_t)r1 * TT + tn) * VOC + i);
                } else { pa[k] = 0.f; pb[k] = 0.f; }
            }
        }

        const float2* xb = xsw + (size_t)(t & 1) * 96;

        layer_step<24>(smem + OFF_W1I, smem + OFF_W1H, xb,
                       hsw + 0,  j, bi1R, bi1Z, bi1N, bh1R, bh1Z, bh1N);
        layer_step<8>(smem + OFF_W2I, smem + OFF_W2H, hsw + 0,
                       hsw + 32, j, bi2R, bi2Z, bi2N, bh2R, bh2Z, bh2N);
        layer_step<8>(smem + OFF_W3I, smem + OFF_W3H, hsw + 32,
                       hsw + 64, j, bi3R, bi3Z, bi3N, bh3R, bh3Z, bh3N);

        // FC head: out = h3 @ Wfc^T + bfc, three 32-wide output groups
        {
            ull a0 = bfc0, a1 = bfc1, a2 = bfc2;
            proj3<8>(smem + OFF_WFC, j, hsw + 64, a0, a1, a2);
            float2 v;
            size_t base0 = ((size_t)r0 * TT + t) * VOC;
            size_t base1 = ((size_t)r1 * TT + t) * VOC;
            int o0 = j, o1 = 32 + j, o2 = 64 + j;
            v = up2(a0); __stcs(out + base0 + o0, v.x); __stcs(out + base1 + o0, v.y);
            v = up2(a1); __stcs(out + base0 + o1, v.x); __stcs(out + base1 + o1, v.y);
            if (o2 < VOC) {
                v = up2(a2); __stcs(out + base0 + o2, v.x); __stcs(out + base1 + o2, v.y);
            }
        }

        // stage prefetched x[t+1] into the other buffer
        if (tn < TT) {
            float2* nb = xsw + (size_t)(tn & 1) * 96;
#pragma unroll
            for (int k = 0; k < 3; k++) {
                int i = j + 32 * k;
                if (i < VOC)
                    nb[i] = make_float2(pa[k], pb[k]);
            }
        }
        __syncwarp();
    }
}

extern "C" void kernel_launch(void* const* d_in, const int* in_sizes, int n_in,
                              void* d_out, int out_size)
{
    const float* x    = (const float*)d_in[0];
    const float* Wih1 = (const float*)d_in[1];
    const float* Whh1 = (const float*)d_in[2];
    const float* bih1 = (const float*)d_in[3];
    const float* bhh1 = (const float*)d_in[4];
    const float* Wih2 = (const float*)d_in[5];
    const float* Whh2 = (const float*)d_in[6];
    const float* bih2 = (const float*)d_in[7];
    const float* bhh2 = (const float*)d_in[8];
    const float* Wih3 = (const float*)d_in[9];
    const float* Whh3 = (const float*)d_in[10];
    const float* bih3 = (const float*)d_in[11];
    const float* bhh3 = (const float*)d_in[12];
    const float* Wfc  = (const float*)d_in[13];
    const float* bfc  = (const float*)d_in[14];
    float* out = (float*)d_out;

    cudaFuncSetAttribute(gru_fused, cudaFuncAttributeMaxDynamicSharedMemorySize,
                         SMEM_BYTES);
    gru_fused<<<NB, NT, SMEM_BYTES>>>(x, Wih1, Whh1, bih1, bhh1,
                                      Wih2, Whh2, bih2, bhh2,
                                      Wih3, Whh3, bih3, bhh3,
                                      Wfc, bfc, out);
}

// round 6
// speedup vs baseline: 1.6195x; 1.6195x over previous
#include <cuda_runtime.h>
#include <cstdint>

using ull = unsigned long long;

#define VOC 95
#define TT  256
#define BB  2048

// ---------------- scratch: xp = x @ Wih1^T + bih1  [B*T, 96] ----------------
__device__ float g_xp[(size_t)BB * TT * 96];

// ---------- packed fp32x2 helpers ----------
__device__ __forceinline__ ull pk2(float w) {
    ull d; unsigned r = __float_as_uint(w);
    asm("mov.b64 %0, {%1,%1};" : "=l"(d) : "r"(r));
    return d;
}
__device__ __forceinline__ ull pkf(float a, float b) {
    ull d;
    asm("mov.b64 %0, {%1,%2};" : "=l"(d)
        : "r"(__float_as_uint(a)), "r"(__float_as_uint(b)));
    return d;
}
__device__ __forceinline__ float2 up2(ull v) {
    unsigned lo, hi;
    asm("mov.b64 {%0,%1}, %2;" : "=r"(lo), "=r"(hi) : "l"(v));
    return make_float2(__uint_as_float(lo), __uint_as_float(hi));
}
__device__ __forceinline__ void fma2(ull& d, ull a, ull b) {
    asm("fma.rn.f32x2 %0, %1, %2, %0;" : "+l"(d) : "l"(a), "l"(b));
}
__device__ __forceinline__ ull add2(ull a, ull b) {
    ull d; asm("add.rn.f32x2 %0, %1, %2;" : "=l"(d) : "l"(a), "l"(b));
    return d;
}

// ---------- activations (MUFU tanh.approx) ----------
__device__ __forceinline__ float tanhap(float v) {
    float r; asm("tanh.approx.f32 %0, %1;" : "=f"(r) : "f"(v)); return r;
}
__device__ __forceinline__ float fsig(float v) {
    return fmaf(tanhap(0.5f * v), 0.5f, 0.5f);
}

extern __shared__ float smem[];

// GMEM weight [3*32, isz] -> SMEM [g][c][lane][4] (i >= isz zero-padded)
__device__ __forceinline__ void load_wmat(float* dst, const float* __restrict__ src,
                                          int C, int isz, int tid, int nthr)
{
    int n = 3 * C * 128;
    for (int idx = tid; idx < n; idx += nthr) {
        int q = idx & 3, jj = (idx >> 2) & 31;
        int c = (idx >> 7) % C, g = idx / (C * 128);
        int i = c * 4 + q;
        dst[idx] = (i < isz) ? src[(g * 32 + jj) * isz + i] : 0.f;
    }
}

// ============================================================================
// Kernel 1: xp[r][96] = x[r][95] @ Wih1^T + bih1   (parallel over all B*T rows)
// 256 blocks x 8 warps; each warp: 16 iters x 8 packed row-pairs (16 rows).
// ============================================================================
#define K1_NB   256
#define K1_NT   256
// smem: W @0 [3][24][32][4]=9216 floats; xs @9216: float2[8 warps][8 pairs][96]
#define K1_XS   9216
#define K1_SMEM_FLOATS (9216 + 8 * 8 * 96 * 2)
#define K1_SMEM_BYTES  (K1_SMEM_FLOATS * 4)

__global__ void __launch_bounds__(K1_NT, 2)
gru_xproj(const float* __restrict__ x,
          const float* __restrict__ Wih1,
          const float* __restrict__ bih1)
{
    const int tid = threadIdx.x;
    load_wmat(smem, Wih1, 24, VOC, tid, K1_NT);
    __syncthreads();

    const int w = tid >> 5, j = tid & 31;
    float2* xsw = (float2*)(smem + K1_XS) + (size_t)w * (8 * 96);

    const ull bR = pk2(bih1[j]), bZ = pk2(bih1[32 + j]), bN = pk2(bih1[64 + j]);
    const size_t pairBase = ((size_t)blockIdx.x * 8 + w) * 128;

#pragma unroll 1
    for (int it = 0; it < 16; it++) {
        const size_t p0 = pairBase + (size_t)it * 8;

        // stage 8 pairs of x rows into SMEM as float2 (rowEven, rowOdd)
#pragma unroll
        for (int p = 0; p < 8; p++) {
            size_t r0 = (p0 + p) * 2, r1 = r0 + 1;
#pragma unroll
            for (int k = 0; k < 3; k++) {
                int i = j + 32 * k;
                float a = 0.f, b = 0.f;
                if (i < VOC) {
                    a = __ldcs(x + r0 * VOC + i);
                    b = __ldcs(x + r1 * VOC + i);
                }
                xsw[p * 96 + i] = make_float2(a, b);
            }
        }
        __syncwarp();

        ull acc[8][3];
#pragma unroll
        for (int p = 0; p < 8; p++) { acc[p][0] = bR; acc[p][1] = bZ; acc[p][2] = bN; }

#pragma unroll 2
        for (int c = 0; c < 24; c++) {
            float4 wA = *(const float4*)(smem + ((0 * 24 + c) * 32 + j) * 4);
            float4 wB = *(const float4*)(smem + ((1 * 24 + c) * 32 + j) * 4);
            float4 wC = *(const float4*)(smem + ((2 * 24 + c) * 32 + j) * 4);
            ull a0 = pk2(wA.x), a1 = pk2(wA.y), a2 = pk2(wA.z), a3 = pk2(wA.w);
            ull b0 = pk2(wB.x), b1 = pk2(wB.y), b2 = pk2(wB.z), b3 = pk2(wB.w);
            ull c0 = pk2(wC.x), c1 = pk2(wC.y), c2 = pk2(wC.z), c3 = pk2(wC.w);
#pragma unroll
            for (int p = 0; p < 8; p++) {
                ulonglong2 x01 = *(const ulonglong2*)(xsw + p * 96 + 4 * c);
                ulonglong2 x23 = *(const ulonglong2*)(xsw + p * 96 + 4 * c + 2);
                fma2(acc[p][0], x01.x, a0); fma2(acc[p][0], x01.y, a1);
                fma2(acc[p][0], x23.x, a2); fma2(acc[p][0], x23.y, a3);
                fma2(acc[p][1], x01.x, b0); fma2(acc[p][1], x01.y, b1);
                fma2(acc[p][1], x23.x, b2); fma2(acc[p][1], x23.y, b3);
                fma2(acc[p][2], x01.x, c0); fma2(acc[p][2], x01.y, c1);
                fma2(acc[p][2], x23.x, c2); fma2(acc[p][2], x23.y, c3);
            }
        }

        // write xp
#pragma unroll
        for (int p = 0; p < 8; p++) {
            size_t r0 = (p0 + p) * 2, r1 = r0 + 1;
#pragma unroll
            for (int g = 0; g < 3; g++) {
                float2 v = up2(acc[p][g]);
                g_xp[r0 * 96 + g * 32 + j] = v.x;
                g_xp[r1 * 96 + g * 32 + j] = v.y;
            }
        }
        __syncwarp();
    }
}

// ============================================================================
// Kernel 2: fused 3-layer GRU scan + FC head, reading precomputed xp.
// 128 blocks x 4 warps; warp owns 4 batch rows (2 packed pairs), all 256 steps.
// ============================================================================
#define NW  4
#define NT2 (NW * 32)
#define NB  128

// smem floats: W1H@0(3072) W2I@3072 W2H@6144 W3I@9216 W3H@12288 WFC@15360
// HS@18432: float2 hs[4 warps][3 layers][2 pairs][32] = 1536 floats
#define OFF_W1H 0
#define OFF_W2I 3072
#define OFF_W2H 6144
#define OFF_W3I 9216
#define OFF_W3H 12288
#define OFF_WFC 15360
#define OFF_HS  18432
#define K2_SMEM_FLOATS (18432 + 1536)
#define K2_SMEM_BYTES  (K2_SMEM_FLOATS * 4)

// ---------- 3-gate projection over C 4-wide input chunks, 2 packed pairs ----
template<int C>
__device__ __forceinline__ void proj3(const float* __restrict__ W, int j,
                                      const float2* __restrict__ in0,
                                      const float2* __restrict__ in1,
                                      ull& aA0, ull& aB0, ull& aC0,
                                      ull& aA1, ull& aB1, ull& aC1)
{
#pragma unroll
    for (int c = 0; c < C; c++) {
        float4 wA = *(const float4*)(W + ((0 * C + c) * 32 + j) * 4);
        float4 wB = *(const float4*)(W + ((1 * C + c) * 32 + j) * 4);
        float4 wC = *(const float4*)(W + ((2 * C + c) * 32 + j) * 4);
        ulonglong2 x01 = *(const ulonglong2*)(in0 + 4 * c);
        ulonglong2 x23 = *(const ulonglong2*)(in0 + 4 * c + 2);
        ulonglong2 y01 = *(const ulonglong2*)(in1 + 4 * c);
        ulonglong2 y23 = *(const ulonglong2*)(in1 + 4 * c + 2);
        ull w;
        w = pk2(wA.x); fma2(aA0, x01.x, w); fma2(aA1, y01.x, w);
        w = pk2(wA.y); fma2(aA0, x01.y, w); fma2(aA1, y01.y, w);
        w = pk2(wA.z); fma2(aA0, x23.x, w); fma2(aA1, y23.x, w);
        w = pk2(wA.w); fma2(aA0, x23.y, w); fma2(aA1, y23.y, w);
        w = pk2(wB.x); fma2(aB0, x01.x, w); fma2(aB1, y01.x, w);
        w = pk2(wB.y); fma2(aB0, x01.y, w); fma2(aB1, y01.y, w);
        w = pk2(wB.z); fma2(aB0, x23.x, w); fma2(aB1, y23.x, w);
        w = pk2(wB.w); fma2(aB0, x23.y, w); fma2(aB1, y23.y, w);
        w = pk2(wC.x); fma2(aC0, x01.x, w); fma2(aC1, y01.x, w);
        w = pk2(wC.y); fma2(aC0, x01.y, w); fma2(aC1, y01.y, w);
        w = pk2(wC.z); fma2(aC0, x23.x, w); fma2(aC1, y23.x, w);
        w = pk2(wC.w); fma2(aC0, x23.y, w); fma2(aC1, y23.y, w);
    }
}

// ---------- GRU elementwise for one packed row-pair ----------
__device__ __forceinline__ ull gru_pair(ull aR, ull aZ, ull aNx, ull aNh, ull h)
{
    float2 r2 = up2(aR), z2 = up2(aZ), nx = up2(aNx), nh = up2(aNh), hh = up2(h);
    float r0 = fsig(r2.x), r1 = fsig(r2.y);
    float z0 = fsig(z2.x), z1 = fsig(z2.y);
    float n0 = tanhap(nx.x + r0 * nh.x);
    float n1 = tanhap(nx.y + r1 * nh.y);
    float h0 = n0 + z0 * (hh.x - n0);
    float h1 = n1 + z1 * (hh.y - n1);
    return pkf(h0, h1);
}

// One GRU layer step (layers 2,3): input from SMEM, 2 pairs.
__device__ __forceinline__ void layer_step8(const float* __restrict__ Wi,
                                            const float* __restrict__ Wh,
                                            const float2* __restrict__ in0,
                                            const float2* __restrict__ in1,
                                            float2* hbuf, int j,
                                            ull biR, ull biZ, ull biN,
                                            ull bhR, ull bhZ, ull bhN)
{
    ull xR0 = biR, xZ0 = biZ, xN0 = biN, xR1 = biR, xZ1 = biZ, xN1 = biN;
    proj3<8>(Wi, j, in0, in1, xR0, xZ0, xN0, xR1, xZ1, xN1);
    ull hR0 = bhR, hZ0 = bhZ, hN0 = bhN, hR1 = bhR, hZ1 = bhZ, hN1 = bhN;
    proj3<8>(Wh, j, hbuf, hbuf + 32, hR0, hZ0, hN0, hR1, hZ1, hN1);
    ull h0 = *(const ull*)(hbuf + j);
    ull h1 = *(const ull*)(hbuf + 32 + j);
    __syncwarp();
    ull n0 = gru_pair(add2(xR0, hR0), add2(xZ0, hZ0), xN0, hN0, h0);
    ull n1 = gru_pair(add2(xR1, hR1), add2(xZ1, hZ1), xN1, hN1, h1);
    *(ull*)(hbuf + j) = n0;
    *(ull*)(hbuf + 32 + j) = n1;
    __syncwarp();
}

__global__ void __launch_bounds__(NT2, 1)
gru_scan(const float* __restrict__ Whh1, const float* __restrict__ bhh1,
         const float* __restrict__ Wih2, const float* __restrict__ Whh2,
         const float* __restrict__ bih2, const float* __restrict__ bhh2,
         const float* __restrict__ Wih3, const float* __restrict__ Whh3,
         const float* __restrict__ bih3, const float* __restrict__ bhh3,
         const float* __restrict__ Wfc,  const float* __restrict__ bfc,
         float* __restrict__ out)
{
    const int tid = threadIdx.x;

    load_wmat(smem + OFF_W1H, Whh1, 8, 32, tid, NT2);
    load_wmat(smem + OFF_W2I, Wih2, 8, 32, tid, NT2);
    load_wmat(smem + OFF_W2H, Whh2, 8, 32, tid, NT2);
    load_wmat(smem + OFF_W3I, Wih3, 8, 32, tid, NT2);
    load_wmat(smem + OFF_W3H, Whh3, 8, 32, tid, NT2);
    {   // FC: output o = g*32+j (pad o=95), input k = c*4+q; src Wfc[o*32+k]
        float* dst = smem + OFF_WFC;
        for (int idx = tid; idx < 3 * 8 * 128; idx += NT2) {
            int q = idx & 3, jj = (idx >> 2) & 31;
            int c = (idx >> 7) % 8, g = idx / (8 * 128);
            int o = g * 32 + jj, k = c * 4 + q;
            dst[idx] = (o < VOC) ? Wfc[o * 32 + k] : 0.f;
        }
    }
    // zero h-state (h0 = 0)
    for (int idx = tid; idx < K2_SMEM_FLOATS - OFF_HS; idx += NT2)
        smem[OFF_HS + idx] = 0.f;
    __syncthreads();

    const int w = tid >> 5, j = tid & 31;
    const int gw = blockIdx.x * NW + w;
    const int rb = gw * 4;             // 4 batch rows per warp

    float2* hsw = (float2*)(smem + OFF_HS) + (size_t)w * (3 * 2 * 32);

    // per-lane bias packs
    ull bh1R = pk2(bhh1[j]), bh1Z = pk2(bhh1[32 + j]), bh1N = pk2(bhh1[64 + j]);
    ull bi2R = pk2(bih2[j]), bi2Z = pk2(bih2[32 + j]), bi2N = pk2(bih2[64 + j]);
    ull bh2R = pk2(bhh2[j]), bh2Z = pk2(bhh2[32 + j]), bh2N = pk2(bhh2[64 + j]);
    ull bi3R = pk2(bih3[j]), bi3Z = pk2(bih3[32 + j]), bi3N = pk2(bih3[64 + j]);
    ull bh3R = pk2(bhh3[j]), bh3Z = pk2(bhh3[32 + j]), bh3N = pk2(bhh3[64 + j]);
    float bf0 = (j      < VOC) ? bfc[j]      : 0.f;
    float bf1 = (32 + j < VOC) ? bfc[32 + j] : 0.f;
    float bf2 = (64 + j < VOC) ? bfc[64 + j] : 0.f;
    ull bfc0 = pk2(bf0), bfc1 = pk2(bf1), bfc2 = pk2(bf2);

    // row bases into xp [row][t][96]
    const size_t xb0 = (size_t)(rb + 0) * TT * 96;
    const size_t xb1 = (size_t)(rb + 1) * TT * 96;
    const size_t xb2 = (size_t)(rb + 2) * TT * 96;
    const size_t xb3 = (size_t)(rb + 3) * TT * 96;

    // cur[pair][gate] = packed xp gate values for this timestep
    ull cur[2][3];
#pragma unroll
    for (int g = 0; g < 3; g++) {
        int o = g * 32 + j;
        cur[0][g] = pkf(__ldcs(g_xp + xb0 + o), __ldcs(g_xp + xb1 + o));
        cur[1][g] = pkf(__ldcs(g_xp + xb2 + o), __ldcs(g_xp + xb3 + o));
    }

#pragma unroll 1
    for (int t = 0; t < TT; t++) {
        // prefetch xp[t+1]
        float nf[2][3][2];
        const int tn = t + 1;
        if (tn < TT) {
            const size_t toff = (size_t)tn * 96;
#pragma unroll
            for (int g = 0; g < 3; g++) {
                int o = g * 32 + j;
                nf[0][g][0] = __ldcs(g_xp + xb0 + toff + o);
                nf[0][g][1] = __ldcs(g_xp + xb1 + toff + o);
                nf[1][g][0] = __ldcs(g_xp + xb2 + toff + o);
                nf[1][g][1] = __ldcs(g_xp + xb3 + toff + o);
            }
        }

        // ---- Layer 1: hidden proj only; input proj comes from xp ----
        {
            ull hR0 = bh1R, hZ0 = bh1Z, hN0 = bh1N;
            ull hR1 = bh1R, hZ1 = bh1Z, hN1 = bh1N;
            proj3<8>(smem + OFF_W1H, j, hsw + 0, hsw + 32,
                     hR0, hZ0, hN0, hR1, hZ1, hN1);
            ull h0 = *(const ull*)(hsw + j);
            ull h1 = *(const ull*)(hsw + 32 + j);
            __syncwarp();
            ull n0 = gru_pair(add2(cur[0][0], hR0), add2(cur[0][1], hZ0),
                              cur[0][2], hN0, h0);
            ull n1 = gru_pair(add2(cur[1][0], hR1), add2(cur[1][1], hZ1),
                              cur[1][2], hN1, h1);
            *(ull*)(hsw + j) = n0;
            *(ull*)(hsw + 32 + j) = n1;
            __syncwarp();
        }

        layer_step8(smem + OFF_W2I, smem + OFF_W2H, hsw + 0, hsw + 32,
                    hsw + 64,  j, bi2R, bi2Z, bi2N, bh2R, bh2Z, bh2N);
        layer_step8(smem + OFF_W3I, smem + OFF_W3H, hsw + 64, hsw + 96,
                    hsw + 128, j, bi3R, bi3Z, bi3N, bh3R, bh3Z, bh3N);

        // FC head: out = h3 @ Wfc^T + bfc
        {
            ull a00 = bfc0, a10 = bfc1, a20 = bfc2;
            ull a01 = bfc0, a11 = bfc1, a21 = bfc2;
            proj3<8>(smem + OFF_WFC, j, hsw + 128, hsw + 160,
                     a00, a10, a20, a01, a11, a21);
            float2 v;
            size_t base0 = ((size_t)(rb + 0) * TT + t) * VOC;
            size_t base1 = ((size_t)(rb + 1) * TT + t) * VOC;
            size_t base2 = ((size_t)(rb + 2) * TT + t) * VOC;
            size_t base3 = ((size_t)(rb + 3) * TT + t) * VOC;
            int o0 = j, o1 = 32 + j, o2 = 64 + j;
            v = up2(a00); __stcs(out + base0 + o0, v.x); __stcs(out + base1 + o0, v.y);
            v = up2(a01); __stcs(out + base2 + o0, v.x); __stcs(out + base3 + o0, v.y);
            v = up2(a10); __stcs(out + base0 + o1, v.x); __stcs(out + base1 + o1, v.y);
            v = up2(a11); __stcs(out + base2 + o1, v.x); __stcs(out + base3 + o1, v.y);
            if (o2 < VOC) {
                v = up2(a20); __stcs(out + base0 + o2, v.x); __stcs(out + base1 + o2, v.y);
                v = up2(a21); __stcs(out + base2 + o2, v.x); __stcs(out + base3 + o2, v.y);
            }
        }

        // roll prefetched values into cur
        if (tn < TT) {
#pragma unroll
            for (int g = 0; g < 3; g++) {
                cur[0][g] = pkf(nf[0][g][0], nf[0][g][1]);
                cur[1][g] = pkf(nf[1][g][0], nf[1][g][1]);
            }
        }
    }
}

extern "C" void kernel_launch(void* const* d_in, const int* in_sizes, int n_in,
                              void* d_out, int out_size)
{
    const float* x    = (const float*)d_in[0];
    const float* Wih1 = (const float*)d_in[1];
    const float* Whh1 = (const float*)d_in[2];
    const float* bih1 = (const float*)d_in[3];
    const float* bhh1 = (const float*)d_in[4];
    const float* Wih2 = (const float*)d_in[5];
    const float* Whh2 = (const float*)d_in[6];
    const float* bih2 = (const float*)d_in[7];
    const float* bhh2 = (const float*)d_in[8];
    const float* Wih3 = (const float*)d_in[9];
    const float* Whh3 = (const float*)d_in[10];
    const float* bih3 = (const float*)d_in[11];
    const float* bhh3 = (const float*)d_in[12];
    const float* Wfc  = (const float*)d_in[13];
    const float* bfc  = (const float*)d_in[14];
    float* out = (float*)d_out;

    cudaFuncSetAttribute(gru_xproj, cudaFuncAttributeMaxDynamicSharedMemorySize,
                         K1_SMEM_BYTES);
    cudaFuncSetAttribute(gru_scan, cudaFuncAttributeMaxDynamicSharedMemorySize,
                         K2_SMEM_BYTES);

    gru_xproj<<<K1_NB, K1_NT, K1_SMEM_BYTES>>>(x, Wih1, bih1);
    gru_scan<<<NB, NT2, K2_SMEM_BYTES>>>(Whh1, bhh1,
                                         Wih2, Whh2, bih2, bhh2,
                                         Wih3, Whh3, bih3, bhh3,
                                         Wfc, bfc, out);
}